// round 16
// baseline (speedup 1.0000x reference)
#include <cuda_runtime.h>
#include <cuda_fp16.h>
#include <stdint.h>

#define P_PTS 200000
#define C_CH  32
#define N_B   4
#define K_FR  8
#define H_IMG 256
#define W_IMG 256
#define TILE  32                 // pixels per block
#define TPR   (W_IMG / TILE)     // 8 tiles per image row

// Transposed + fp16 point features: (P, C) half = 64B per point.
__device__ __half2 g_tab2[P_PTS * (C_CH / 2)];   // 12.8 MB

// ---------------------------------------------------------------------------
// Kernel 1: transpose + downconvert ptclds (C,P) f32 -> (P,C) f16.
// ---------------------------------------------------------------------------
__global__ void __launch_bounds__(256) transpose_kernel(const float* __restrict__ ptclds) {
    __shared__ float tile[32][65];   // 32 channels x 64 points, padded
    const int p0  = blockIdx.x * 64;
    const int tid = threadIdx.x;

    {
        const int c   = tid >> 3;
        const int col = (tid & 7) * 8;
        const float4* src = reinterpret_cast<const float4*>(ptclds + c * P_PTS + p0 + col);
        const float4 v0 = src[0];
        const float4 v1 = src[1];
        tile[c][col + 0] = v0.x; tile[c][col + 1] = v0.y;
        tile[c][col + 2] = v0.z; tile[c][col + 3] = v0.w;
        tile[c][col + 4] = v1.x; tile[c][col + 5] = v1.y;
        tile[c][col + 6] = v1.z; tile[c][col + 7] = v1.w;
    }
    __syncthreads();

#pragma unroll
    for (int i = 0; i < 4; i++) {
        const int idx = tid + i * 256;
        const int pl  = idx >> 4;    // point within tile
        const int cp  = idx & 15;    // channel pair
        g_tab2[(p0 + pl) * (C_CH / 2) + cp] =
            __floats2half2_rn(tile[cp * 2][pl], tile[cp * 2 + 1][pl]);
    }
}

// ---------------------------------------------------------------------------
// Kernel 2: composite. R15 structure (warp-0 weight precompute + 4 px/warp
// L1-bypassed gather) with instruction/wavefront cuts:
//   - s_wp pixel-major [TILE][K_FR+2] (80B rows, 16B aligned): weight loop
//     reads 2 k per LDS.128 (conflict-free; bases 0/20/40/60 words mod 32
//     give disjoint 4-word segments for every i).
//   - epilogue: one float4 STG.128 per thread, single pass.
// ---------------------------------------------------------------------------
__global__ void __launch_bounds__(256) composite_kernel(
    const int*   __restrict__ frags,
    const float* __restrict__ alphas,
    float*       __restrict__ out)
{
    __shared__ int2  s_wp[TILE][K_FR + 2];    // (wgt bits, quad-offset), 80B rows
    __shared__ float s_out[C_CH][TILE + 1];   // stride 33: conflict-free

    const int b   = blockIdx.x;
    const int n   = b / (H_IMG * TPR);
    const int rem = b % (H_IMG * TPR);
    const int h   = rem / TPR;
    const int w0  = (rem % TPR) * TILE;

    const int tid = threadIdx.x;

    // Phase 1: warp 0 computes per-pixel weights+offsets, one thread/pixel.
    // All 16 loads issued before the dependent transmittance chain.
    if (tid < TILE) {
        const int pbase = ((n * K_FR) * H_IMG + h) * W_IMG + w0 + tid;
        int   p[K_FR];
        float a[K_FR];
#pragma unroll
        for (int kk = 0; kk < K_FR; kk++) {
            const int off = pbase + kk * (H_IMG * W_IMG);
            p[kk] = __ldcs(frags + off);
            a[kk] = __ldcs(alphas + off);
        }
        float T = 1.0f;
        int4* dst = reinterpret_cast<int4*>(s_wp[tid]);
#pragma unroll
        for (int i = 0; i < 4; i++) {
            int   k0 = 2 * i, k1 = 2 * i + 1;
            const bool  v0 = (p[k0] >= 0);
            const float a0 = v0 ? a[k0] : 0.0f;
            const float w0f = a0 * T;
            T *= (1.0f - a0);
            int pc0 = v0 ? p[k0] : 0;
            pc0 = (pc0 < P_PTS) ? pc0 : (P_PTS - 1);

            const bool  v1 = (p[k1] >= 0);
            const float a1 = v1 ? a[k1] : 0.0f;
            const float w1f = a1 * T;
            T *= (1.0f - a1);
            int pc1 = v1 ? p[k1] : 0;
            pc1 = (pc1 < P_PTS) ? pc1 : (P_PTS - 1);

            dst[i] = make_int4(__float_as_int(w0f), pc0 * (C_CH / 4),
                               __float_as_int(w1f), pc1 * (C_CH / 4));
        }
    }
    __syncthreads();

    const int lane = tid & 31;
    const int wid  = tid >> 5;               // warp id 0..7
    const int pi   = wid * 4 + (lane >> 3);  // pixel within 32-pixel tile
    const int cq   = lane & 7;               // channel quad 0..7

    // Phase 2: 8 independent L1-bypassed LDG.64 gathers + fp32 FMA reduce.
    const uint2* __restrict__ tab = reinterpret_cast<const uint2*>(g_tab2);
    const int4*  __restrict__ wp4 = reinterpret_cast<const int4*>(s_wp[pi]);
    float4 acc = make_float4(0.0f, 0.0f, 0.0f, 0.0f);
#pragma unroll
    for (int i = 0; i < 4; i++) {
        const int4 wp = wp4[i];               // 2 k-entries per LDS.128

        const uint2  r0  = __ldcg(tab + wp.y + cq);
        const float  wA  = __int_as_float(wp.x);
        const float2 a01 = __half22float2(*reinterpret_cast<const __half2*>(&r0.x));
        const float2 a23 = __half22float2(*reinterpret_cast<const __half2*>(&r0.y));
        acc.x += wA * a01.x;  acc.y += wA * a01.y;
        acc.z += wA * a23.x;  acc.w += wA * a23.y;

        const uint2  r1  = __ldcg(tab + wp.w + cq);
        const float  wB  = __int_as_float(wp.z);
        const float2 b01 = __half22float2(*reinterpret_cast<const __half2*>(&r1.x));
        const float2 b23 = __half22float2(*reinterpret_cast<const __half2*>(&r1.y));
        acc.x += wB * b01.x;  acc.y += wB * b01.y;
        acc.z += wB * b23.x;  acc.w += wB * b23.y;
    }

    // Scatter: banks (4cq + j + pi) mod 32 distinct per warp -> conflict-free.
    s_out[cq * 4 + 0][pi] = acc.x;
    s_out[cq * 4 + 1][pi] = acc.y;
    s_out[cq * 4 + 2][pi] = acc.z;
    s_out[cq * 4 + 3][pi] = acc.w;
    __syncthreads();

    // Epilogue: one float4 per thread (c = tid>>3, 4 consecutive pixels).
    // LDS.32 x4 conflict-free (banks c + pw4 + j distinct); STG.128 coalesced.
    {
        const int c   = tid >> 3;
        const int pw4 = (tid & 7) * 4;
        const float4 v = make_float4(s_out[c][pw4 + 0], s_out[c][pw4 + 1],
                                     s_out[c][pw4 + 2], s_out[c][pw4 + 3]);
        __stcs(reinterpret_cast<float4*>(
                   out + ((n * C_CH + c) * H_IMG + h) * W_IMG + w0 + pw4), v);
    }
}

extern "C" void kernel_launch(void* const* d_in, const int* in_sizes, int n_in,
                              void* d_out, int out_size) {
    const int*   frags  = (const int*)d_in[0];    // int32 (N,K,H,W)
    const float* alphas = (const float*)d_in[1];  // f32   (N,K,H,W)
    const float* ptclds = (const float*)d_in[2];  // f32   (C,P)
    float*       out    = (float*)d_out;          // f32   (N,C,H,W)

    transpose_kernel<<<P_PTS / 64, 256>>>(ptclds);
    composite_kernel<<<N_B * H_IMG * TPR, 256>>>(frags, alphas, out);
}